// round 1
// baseline (speedup 1.0000x reference)
#include <cuda_runtime.h>
#include <math.h>

#define NNODES 40000
#define NEDGES 480000
#define NGRAPH 160
#define NPG    250
#define DOUT   3072
#define HID    1536

// ---------------- scratch (device globals; no allocation allowed) ----------------
__device__ float d_F[(size_t)NNODES * DOUT];     // concat buffer: c1|c2|c3|c4
__device__ float d_H[(size_t)NNODES * 1024];     // per-layer GEMM output h = x@W
__device__ float d_AS[NNODES * 4];               // per-node per-head src attention scalar
__device__ float d_AD[NNODES * 4];               // per-node per-head dst attention scalar
__device__ int   d_rowptr[NNODES + 1];
__device__ int   d_deg[NNODES];
__device__ int   d_cur[NNODES];
__device__ int   d_csr[NEDGES];                  // src ids grouped by dst
__device__ float d_pooled[NGRAPH * DOUT];
__device__ float d_h1[NGRAPH * HID];

// ---------------- small helpers ----------------
__device__ __forceinline__ float warpSum(float v) {
    #pragma unroll
    for (int o = 16; o; o >>= 1) v += __shfl_xor_sync(0xffffffffu, v, o);
    return v;
}
__device__ __forceinline__ float warpMax(float v) {
    #pragma unroll
    for (int o = 16; o; o >>= 1) v = fmaxf(v, __shfl_xor_sync(0xffffffffu, v, o));
    return v;
}
__device__ __forceinline__ float lrelu(float x) { return x > 0.f ? x : 0.2f * x; }

// ---------------- CSR build ----------------
__global__ void k_zero() {
    int i = blockIdx.x * blockDim.x + threadIdx.x;
    if (i < NNODES) { d_deg[i] = 0; d_cur[i] = 0; }
}

__global__ void k_count(const int* __restrict__ ei) {
    int e = blockIdx.x * blockDim.x + threadIdx.x;
    if (e < NEDGES) atomicAdd(&d_deg[ei[NEDGES + e]], 1);
}

__global__ void k_scan() {
    __shared__ int s[1024];
    __shared__ int s_carry;
    int tid = threadIdx.x;
    if (tid == 0) s_carry = 0;
    __syncthreads();
    for (int base = 0; base < NNODES; base += 1024) {
        int v = (base + tid < NNODES) ? d_deg[base + tid] : 0;
        s[tid] = v;
        __syncthreads();
        for (int off = 1; off < 1024; off <<= 1) {
            int t = (tid >= off) ? s[tid - off] : 0;
            __syncthreads();
            s[tid] += t;
            __syncthreads();
        }
        if (base + tid < NNODES) d_rowptr[base + tid] = s_carry + s[tid] - v;
        __syncthreads();
        if (tid == 0) s_carry += s[1023];
        __syncthreads();
    }
    if (tid == 0) d_rowptr[NNODES] = s_carry;
}

__global__ void k_fill(const int* __restrict__ ei) {
    int e = blockIdx.x * blockDim.x + threadIdx.x;
    if (e < NEDGES) {
        int sn = ei[e];
        int dn = ei[NEDGES + e];
        int p = d_rowptr[dn] + atomicAdd(&d_cur[dn], 1);
        d_csr[p] = sn;
    }
}

// ---------------- GEMM: C[M,Nc] = A[M,K] @ W[K,Nc] ----------------
// 128x128 block tile, BK=8, 256 threads, 8x8 microtile, fp32.
__global__ __launch_bounds__(256) void k_gemm(const float* __restrict__ A,
                                              const float* __restrict__ W,
                                              float* __restrict__ C,
                                              int M, int K, int Nc, int lda, int ldc) {
    __shared__ float As[8][132];
    __shared__ float Bs[8][128];
    int row0 = blockIdx.y * 128;
    int col0 = blockIdx.x * 128;
    int tid = threadIdx.x;
    int tx = tid & 15, ty = tid >> 4;

    float acc[8][8];
    #pragma unroll
    for (int i = 0; i < 8; i++)
        #pragma unroll
        for (int j = 0; j < 8; j++) acc[i][j] = 0.f;

    int amm = tid >> 1;            // A row within tile
    int akv = (tid & 1) * 4;       // A k sub-offset
    int bkk = tid >> 5;            // B k row
    int bnn = (tid & 31) * 4;      // B col sub-offset

    for (int k0 = 0; k0 < K; k0 += 8) {
        float4 av = make_float4(0.f, 0.f, 0.f, 0.f);
        if (row0 + amm < M)
            av = *(const float4*)(A + (size_t)(row0 + amm) * lda + k0 + akv);
        As[akv + 0][amm] = av.x;
        As[akv + 1][amm] = av.y;
        As[akv + 2][amm] = av.z;
        As[akv + 3][amm] = av.w;
        float4 bv = *(const float4*)(W + (size_t)(k0 + bkk) * Nc + col0 + bnn);
        *(float4*)&Bs[bkk][bnn] = bv;
        __syncthreads();
        #pragma unroll
        for (int kk = 0; kk < 8; kk++) {
            float4 a0 = *(float4*)&As[kk][ty * 8];
            float4 a1 = *(float4*)&As[kk][ty * 8 + 4];
            float4 b0 = *(float4*)&Bs[kk][tx * 8];
            float4 b1 = *(float4*)&Bs[kk][tx * 8 + 4];
            float a[8] = {a0.x, a0.y, a0.z, a0.w, a1.x, a1.y, a1.z, a1.w};
            float b[8] = {b0.x, b0.y, b0.z, b0.w, b1.x, b1.y, b1.z, b1.w};
            #pragma unroll
            for (int i = 0; i < 8; i++)
                #pragma unroll
                for (int j = 0; j < 8; j++) acc[i][j] = fmaf(a[i], b[j], acc[i][j]);
        }
        __syncthreads();
    }
    #pragma unroll
    for (int i = 0; i < 8; i++) {
        int r = row0 + ty * 8 + i;
        if (r < M) {
            float4 v0 = make_float4(acc[i][0], acc[i][1], acc[i][2], acc[i][3]);
            float4 v1 = make_float4(acc[i][4], acc[i][5], acc[i][6], acc[i][7]);
            *(float4*)(C + (size_t)r * ldc + col0 + tx * 8)     = v0;
            *(float4*)(C + (size_t)r * ldc + col0 + tx * 8 + 4) = v1;
        }
    }
}

// ---------------- per-node attention scalars ----------------
// block=128 (warp per head). AS[n][h] = sum_c H[n][h*C+c]*asrc[h][c]; AD likewise.
__global__ void k_att(const float* __restrict__ asrc, const float* __restrict__ adst,
                      int Cc, int hc) {
    int n = blockIdx.x;
    int w = threadIdx.x >> 5;
    int lane = threadIdx.x & 31;
    const float* h = d_H + (size_t)n * hc + w * Cc;
    const float* as = asrc + w * Cc;
    const float* ad = adst + w * Cc;
    float s1 = 0.f, s2 = 0.f;
    for (int c = lane; c < Cc; c += 32) {
        float v = h[c];
        s1 = fmaf(v, as[c], s1);
        s2 = fmaf(v, ad[c], s2);
    }
    s1 = warpSum(s1);
    s2 = warpSum(s2);
    if (lane == 0) {
        d_AS[n * 4 + w] = s1;
        d_AD[n * 4 + w] = s2;
    }
}

// ---------------- fused softmax + gather-aggregate (one block per dst node) ----------------
__global__ __launch_bounds__(256) void k_agg(const float* __restrict__ bg,
                                             int hc, int cshift, int coff) {
    int n = blockIdx.x;
    int tid = threadIdx.x;
    int lane = tid & 31, wid = tid >> 5;
    int rs = d_rowptr[n];
    int deg = d_rowptr[n + 1] - rs;
    int tot = deg + 1;  // + self loop

    __shared__ float s_m[4], s_dinv[4];
    __shared__ float s_red[8];
    __shared__ int   s_src[128];
    __shared__ float s_al[128 * 4];

    float ad[4];
    #pragma unroll
    for (int h = 0; h < 4; h++) ad[h] = d_AD[n * 4 + h];

    // ---- pass 1: per-head max ----
    float lm[4] = {-1e30f, -1e30f, -1e30f, -1e30f};
    for (int i = tid; i < tot; i += 256) {
        int s = (i < deg) ? d_csr[rs + i] : n;
        #pragma unroll
        for (int h = 0; h < 4; h++) {
            float e = lrelu(d_AS[s * 4 + h] + ad[h]);
            lm[h] = fmaxf(lm[h], e);
        }
    }
    #pragma unroll
    for (int h = 0; h < 4; h++) {
        float v = warpMax(lm[h]);
        if (lane == 0) s_red[wid] = v;
        __syncthreads();
        if (tid == 0) {
            float m = s_red[0];
            #pragma unroll
            for (int w2 = 1; w2 < 8; w2++) m = fmaxf(m, s_red[w2]);
            s_m[h] = m;
        }
        __syncthreads();
    }

    // ---- pass 2: per-head sum of exp ----
    float ls[4] = {0.f, 0.f, 0.f, 0.f};
    for (int i = tid; i < tot; i += 256) {
        int s = (i < deg) ? d_csr[rs + i] : n;
        #pragma unroll
        for (int h = 0; h < 4; h++) {
            float e = lrelu(d_AS[s * 4 + h] + ad[h]);
            ls[h] += __expf(e - s_m[h]);
        }
    }
    #pragma unroll
    for (int h = 0; h < 4; h++) {
        float v = warpSum(ls[h]);
        if (lane == 0) s_red[wid] = v;
        __syncthreads();
        if (tid == 0) {
            float t = 0.f;
            #pragma unroll
            for (int w2 = 0; w2 < 8; w2++) t += s_red[w2];
            s_dinv[h] = 1.f / (t + 1e-16f);
        }
        __syncthreads();
    }

    // ---- pass 3: weighted gather-accumulate ----
    float acc[4] = {0.f, 0.f, 0.f, 0.f};
    int kmax = hc >> 8;  // 2 or 4 channels per thread
    for (int base = 0; base < tot; base += 128) {
        int cnt = min(128, tot - base);
        if (tid < cnt) {
            int i = base + tid;
            int s = (i < deg) ? d_csr[rs + i] : n;
            s_src[tid] = s;
            #pragma unroll
            for (int h = 0; h < 4; h++) {
                float e = lrelu(d_AS[s * 4 + h] + ad[h]);
                s_al[tid * 4 + h] = __expf(e - s_m[h]) * s_dinv[h];
            }
        }
        __syncthreads();
        for (int j = 0; j < cnt; j++) {
            int s = s_src[j];
            const float* hp = d_H + (size_t)s * hc;
            #pragma unroll
            for (int k = 0; k < 4; k++) {
                if (k < kmax) {
                    int c = tid + (k << 8);
                    acc[k] = fmaf(s_al[j * 4 + (c >> cshift)], hp[c], acc[k]);
                }
            }
        }
        __syncthreads();
    }
    float* outp = d_F + (size_t)n * DOUT + coff;
    #pragma unroll
    for (int k = 0; k < 4; k++) {
        if (k < kmax) {
            int c = tid + (k << 8);
            outp[c] = acc[k] + bg[c];
        }
    }
}

// ---------------- pooling: mean over 250 contiguous nodes, fused ReLU ----------------
__global__ void k_pool() {
    int g = blockIdx.x;
    for (int c = threadIdx.x; c < DOUT; c += 256) {
        const float* p = d_F + (size_t)g * NPG * DOUT + c;
        float s = 0.f;
        for (int r = 0; r < NPG; r++) {
            float v = p[(size_t)r * DOUT];
            s += v > 0.f ? v : 0.f;
        }
        d_pooled[g * DOUT + c] = s * (1.f / (float)NPG);
    }
}

// ---------------- dense 1: h1 = relu(pooled @ Wd1 + bd1) ----------------
__global__ void k_dense1(const float* __restrict__ Wd1, const float* __restrict__ bd1) {
    __shared__ float sp[DOUT];
    int g = blockIdx.x;
    for (int c = threadIdx.x; c < DOUT; c += 256) sp[c] = d_pooled[g * DOUT + c];
    __syncthreads();
    for (int j = threadIdx.x; j < HID; j += 256) {
        float a = bd1[j];
        for (int k = 0; k < DOUT; k++) a = fmaf(sp[k], Wd1[(size_t)k * HID + j], a);
        d_h1[g * HID + j] = a > 0.f ? a : 0.f;
    }
}

// ---------------- layernorm + final linear ----------------
__global__ void k_final(const float* __restrict__ gln, const float* __restrict__ bln,
                        const float* __restrict__ Wd2, const float* __restrict__ bd2,
                        float* __restrict__ out) {
    int g = blockIdx.x;
    int tid = threadIdx.x, lane = tid & 31, wid = tid >> 5;
    __shared__ float sred[8];
    __shared__ float s_mu, s_rstd, s_dot;
    const float* h = d_h1 + g * HID;

    float s = 0.f;
    for (int j = tid; j < HID; j += 256) s += h[j];
    s = warpSum(s);
    if (lane == 0) sred[wid] = s;
    __syncthreads();
    if (tid == 0) {
        float t = 0.f;
        #pragma unroll
        for (int w = 0; w < 8; w++) t += sred[w];
        s_mu = t / (float)HID;
    }
    __syncthreads();
    float mu = s_mu;

    float v = 0.f;
    for (int j = tid; j < HID; j += 256) {
        float d = h[j] - mu;
        v = fmaf(d, d, v);
    }
    v = warpSum(v);
    if (lane == 0) sred[wid] = v;
    __syncthreads();
    if (tid == 0) {
        float t = 0.f;
        #pragma unroll
        for (int w = 0; w < 8; w++) t += sred[w];
        s_rstd = rsqrtf(t / (float)HID + 1e-5f);
    }
    __syncthreads();
    float rstd = s_rstd;

    float dot = 0.f;
    for (int j = tid; j < HID; j += 256) {
        float xn = (h[j] - mu) * rstd * gln[j] + bln[j];
        dot = fmaf(xn, Wd2[j], dot);
    }
    dot = warpSum(dot);
    if (lane == 0) sred[wid] = dot;
    __syncthreads();
    if (tid == 0) {
        float t = 0.f;
        #pragma unroll
        for (int w = 0; w < 8; w++) t += sred[w];
        out[g] = t + bd2[0] + 0.5f;
    }
}

// ---------------- launch ----------------
extern "C" void kernel_launch(void* const* d_in, const int* in_sizes, int n_in,
                              void* d_out, int out_size) {
    const float* x    = (const float*)d_in[0];
    const int*   ei   = (const int*)d_in[1];
    const float* Wg1  = (const float*)d_in[3];
    const float* as1  = (const float*)d_in[4];
    const float* ad1  = (const float*)d_in[5];
    const float* bg1  = (const float*)d_in[6];
    const float* Wg2  = (const float*)d_in[7];
    const float* as2  = (const float*)d_in[8];
    const float* ad2  = (const float*)d_in[9];
    const float* bg2  = (const float*)d_in[10];
    const float* Wg3  = (const float*)d_in[11];
    const float* as3  = (const float*)d_in[12];
    const float* ad3  = (const float*)d_in[13];
    const float* bg3  = (const float*)d_in[14];
    const float* Wg4  = (const float*)d_in[15];
    const float* as4  = (const float*)d_in[16];
    const float* ad4  = (const float*)d_in[17];
    const float* bg4  = (const float*)d_in[18];
    const float* Wd1  = (const float*)d_in[19];
    const float* bd1  = (const float*)d_in[20];
    const float* gln  = (const float*)d_in[21];
    const float* bln  = (const float*)d_in[22];
    const float* Wd2  = (const float*)d_in[23];
    const float* bd2  = (const float*)d_in[24];

    float* dF = nullptr;
    float* dH = nullptr;
    cudaGetSymbolAddress((void**)&dF, d_F);
    cudaGetSymbolAddress((void**)&dH, d_H);

    // CSR build (dst-grouped)
    k_zero<<<(NNODES + 255) / 256, 256>>>();
    k_count<<<(NEDGES + 255) / 256, 256>>>(ei);
    k_scan<<<1, 1024>>>();
    k_fill<<<(NEDGES + 255) / 256, 256>>>(ei);

    dim3 gRows((0, 0));
    // layer 1: in x [N,768] -> hc 512, C=128, out F[:,0:512)
    {
        dim3 grid(512 / 128, (NNODES + 127) / 128);
        k_gemm<<<grid, 256>>>(x, Wg1, dH, NNODES, 768, 512, 768, 512);
        k_att<<<NNODES, 128>>>(as1, ad1, 128, 512);
        k_agg<<<NNODES, 256>>>(bg1, 512, 7, 0);
    }
    // layer 2: in F[:,0:512) -> hc 512, out F[:,512:1024)
    {
        dim3 grid(512 / 128, (NNODES + 127) / 128);
        k_gemm<<<grid, 256>>>(dF + 0, Wg2, dH, NNODES, 512, 512, DOUT, 512);
        k_att<<<NNODES, 128>>>(as2, ad2, 128, 512);
        k_agg<<<NNODES, 256>>>(bg2, 512, 7, 512);
    }
    // layer 3: in F[:,512:1024) -> hc 1024, C=256, out F[:,1024:2048)
    {
        dim3 grid(1024 / 128, (NNODES + 127) / 128);
        k_gemm<<<grid, 256>>>(dF + 512, Wg3, dH, NNODES, 512, 1024, DOUT, 1024);
        k_att<<<NNODES, 128>>>(as3, ad3, 256, 1024);
        k_agg<<<NNODES, 256>>>(bg3, 1024, 8, 1024);
    }
    // layer 4: in F[:,1024:2048) -> hc 1024, out F[:,2048:3072)
    {
        dim3 grid(1024 / 128, (NNODES + 127) / 128);
        k_gemm<<<grid, 256>>>(dF + 1024, Wg4, dH, NNODES, 1024, 1024, DOUT, 1024);
        k_att<<<NNODES, 128>>>(as4, ad4, 256, 1024);
        k_agg<<<NNODES, 256>>>(bg4, 1024, 8, 2048);
    }

    // head
    k_pool<<<NGRAPH, 256>>>();
    k_dense1<<<NGRAPH, 256>>>(Wd1, bd1);
    k_final<<<NGRAPH, 256>>>(gln, bln, Wd2, bd2, (float*)d_out);
}

// round 4
// speedup vs baseline: 1.6353x; 1.6353x over previous
#include <cuda_runtime.h>
#include <cuda_bf16.h>
#include <math.h>
#include <stdint.h>

#define NNODES 40000
#define MPAD   40064
#define NEDGES 480000
#define NGRAPH 160
#define NPG    250
#define DOUT   3072
#define HID    1536

// ---------------- scratch (device globals) ----------------
__device__ float d_F[(size_t)NNODES * DOUT];     // concat buffer: c1|c2|c3|c4
__device__ float d_H[(size_t)NNODES * 1024];     // per-layer GEMM output h = x@W
__device__ __nv_bfloat16 d_A2[(size_t)MPAD * 2048];  // A split [M, 2K]: [hi | lo]
__device__ __nv_bfloat16 d_W2[4456448];          // per-layer W^T split [N, 2K]
__device__ float d_AS[NNODES * 4];
__device__ float d_AD[NNODES * 4];
__device__ int   d_rowptr[NNODES + 1];
__device__ int   d_deg[NNODES];
__device__ int   d_cur[NNODES];
__device__ int   d_csr[NEDGES];
__device__ float d_pooled[NGRAPH * DOUT];
__device__ float d_h1[NGRAPH * HID];

// ---------------- ptx helpers (baseline ISA only: sm_80-era) ----------------
__device__ __forceinline__ uint32_t smem_u32(const void* p) {
    uint32_t a;
    asm("{ .reg .u64 t; cvta.to.shared.u64 t, %1; cvt.u32.u64 %0, t; }" : "=r"(a) : "l"(p));
    return a;
}

#define CP_ASYNC16(dst, src) \
    asm volatile("cp.async.cg.shared.global [%0], [%1], 16;" :: "r"(dst), "l"(src))
// zero-fills when szp==0 (src-size operand)
#define CP_ASYNC16_Z(dst, src, szp) \
    asm volatile("cp.async.cg.shared.global [%0], [%1], 16, %2;" :: "r"(dst), "l"(src), "r"(szp))
#define CP_COMMIT() asm volatile("cp.async.commit_group;" ::: "memory")
#define CP_WAIT1()  asm volatile("cp.async.wait_group 1;" ::: "memory")
#define CP_WAIT0()  asm volatile("cp.async.wait_group 0;" ::: "memory")

#define LDSM_X4(r, addr) \
    asm volatile("ldmatrix.sync.aligned.m8n8.x4.shared.b16 {%0,%1,%2,%3}, [%4];" \
        : "=r"((r)[0]), "=r"((r)[1]), "=r"((r)[2]), "=r"((r)[3]) : "r"(addr))

#define MMA_16816(d, a, b0, b1) \
    asm volatile("mma.sync.aligned.m16n8k16.row.col.f32.bf16.bf16.f32 " \
        "{%0,%1,%2,%3}, {%4,%5,%6,%7}, {%8,%9}, {%0,%1,%2,%3};" \
        : "+f"((d)[0]), "+f"((d)[1]), "+f"((d)[2]), "+f"((d)[3]) \
        : "r"((a)[0]), "r"((a)[1]), "r"((a)[2]), "r"((a)[3]), "r"(b0), "r"(b1))

// ---------------- small helpers ----------------
__device__ __forceinline__ float warpSum(float v) {
    #pragma unroll
    for (int o = 16; o; o >>= 1) v += __shfl_xor_sync(0xffffffffu, v, o);
    return v;
}
__device__ __forceinline__ float warpMax(float v) {
    #pragma unroll
    for (int o = 16; o; o >>= 1) v = fmaxf(v, __shfl_xor_sync(0xffffffffu, v, o));
    return v;
}
__device__ __forceinline__ float lrelu(float x) { return x > 0.f ? x : 0.2f * x; }

// ---------------- CSR build ----------------
__global__ void k_zero() {
    int i = blockIdx.x * blockDim.x + threadIdx.x;
    if (i < NNODES) { d_deg[i] = 0; d_cur[i] = 0; }
}
__global__ void k_count(const int* __restrict__ ei) {
    int e = blockIdx.x * blockDim.x + threadIdx.x;
    if (e < NEDGES) atomicAdd(&d_deg[ei[NEDGES + e]], 1);
}
__global__ void k_scan() {
    __shared__ int s[1024];
    __shared__ int s_carry;
    int tid = threadIdx.x;
    if (tid == 0) s_carry = 0;
    __syncthreads();
    for (int base = 0; base < NNODES; base += 1024) {
        int v = (base + tid < NNODES) ? d_deg[base + tid] : 0;
        s[tid] = v;
        __syncthreads();
        for (int off = 1; off < 1024; off <<= 1) {
            int t = (tid >= off) ? s[tid - off] : 0;
            __syncthreads();
            s[tid] += t;
            __syncthreads();
        }
        if (base + tid < NNODES) d_rowptr[base + tid] = s_carry + s[tid] - v;
        __syncthreads();
        if (tid == 0) s_carry += s[1023];
        __syncthreads();
    }
    if (tid == 0) d_rowptr[NNODES] = s_carry;
}
__global__ void k_fill(const int* __restrict__ ei) {
    int e = blockIdx.x * blockDim.x + threadIdx.x;
    if (e < NEDGES) {
        int sn = ei[e];
        int dn = ei[NEDGES + e];
        int p = d_rowptr[dn] + atomicAdd(&d_cur[dn], 1);
        d_csr[p] = sn;
    }
}

// ---------------- W prep: W[K,Nc] fp32 -> Wt2 [Nc, 2K] bf16 (hi|lo) ----------------
__global__ void k_prepw(const float* __restrict__ W, __nv_bfloat16* __restrict__ out,
                        int K, int Nc) {
    __shared__ float s[32][33];
    int k0 = blockIdx.y * 32, n0 = blockIdx.x * 32;
    int tx = threadIdx.x & 31, ty = threadIdx.x >> 5;   // 256 threads
    #pragma unroll
    for (int i = 0; i < 32; i += 8)
        s[ty + i][tx] = W[(size_t)(k0 + ty + i) * Nc + n0 + tx];
    __syncthreads();
    #pragma unroll
    for (int i = 0; i < 32; i += 8) {
        float v = s[tx][ty + i];
        __nv_bfloat16 hi = __float2bfloat16(v);
        __nv_bfloat16 lo = __float2bfloat16(v - __bfloat162float(hi));
        size_t n = (size_t)(n0 + ty + i);
        out[n * (2 * K) + k0 + tx]     = hi;
        out[n * (2 * K) + K + k0 + tx] = lo;
    }
}

// ---------------- A prep: A[M,K] fp32 (stride lda) -> d_A2 [M, 2K] ----------------
__global__ void k_cvt(const float* __restrict__ A, int lda, int K) {
    int m = blockIdx.y;
    int k = blockIdx.x * 256 + threadIdx.x;
    float v = A[(size_t)m * lda + k];
    __nv_bfloat16 hi = __float2bfloat16(v);
    __nv_bfloat16 lo = __float2bfloat16(v - __bfloat162float(hi));
    d_A2[(size_t)m * (2 * K) + k]     = hi;
    d_A2[(size_t)m * (2 * K) + K + k] = lo;
}

__global__ void k_zatt() {
    int i = blockIdx.x * 256 + threadIdx.x;
    if (i < NNODES * 4) { d_AS[i] = 0.f; d_AD[i] = 0.f; }
}

// ---------------- HMMA GEMM: C[M,Nc] = A'[M,3K] @ B'[Nc,3K]^T ----------------
// 128x128 tile, BK=32, 8 warps (2Mx4N), cp.async double buffer, fused attention epilogue.
__global__ __launch_bounds__(256, 2) void k_gemm_mma(
    const __nv_bfloat16* __restrict__ A2, const __nv_bfloat16* __restrict__ B2,
    float* __restrict__ C, int K, int Nc,
    const float* __restrict__ asrc, const float* __restrict__ adst, int cshift)
{
    __shared__ __align__(16) unsigned char smem[40960];  // A:2x10240, B:2x10240 (80B rows)
    uint32_t sb = smem_u32(smem);
    const int tid = threadIdx.x, wid = tid >> 5, lane = tid & 31;
    const int row0 = blockIdx.y * 128, col0 = blockIdx.x * 128;
    const int lda = 2 * K;
    const int kc = K >> 5;       // 32-wide chunks per segment
    const int nch = 3 * kc;      // 3 terms: AhBh + AlBh + AhBl
    const int wm = (wid & 1) * 64;
    const int wn = (wid >> 1) * 32;

    float acc[4][4][4];
    #pragma unroll
    for (int a = 0; a < 4; a++)
        #pragma unroll
        for (int b = 0; b < 4; b++)
            #pragma unroll
            for (int q = 0; q < 4; q++) acc[a][b][q] = 0.f;

    auto load_chunk = [&](int c) {
        int seg = c / kc, kk = c - seg * kc;
        int ak = ((seg == 1) ? K : 0) + kk * 32;
        int bk = ((seg == 2) ? K : 0) + kk * 32;
        int b = c & 1;
        uint32_t ab = sb + b * 10240;
        uint32_t bb = sb + 20480 + b * 10240;
        #pragma unroll
        for (int j = 0; j < 2; j++) {
            int q = j * 256 + tid;
            int r = q >> 2, c16 = q & 3;
            int sz = (row0 + r < NNODES) ? 16 : 0;   // zero-fill M pad rows
            CP_ASYNC16_Z(ab + r * 80 + c16 * 16,
                         A2 + (size_t)(row0 + r) * lda + ak + c16 * 8, sz);
            CP_ASYNC16(bb + r * 80 + c16 * 16,
                       B2 + (size_t)(col0 + r) * lda + bk + c16 * 8);
        }
    };

    const int lrow = lane & 15, lk = (lane >> 4) << 3;

    auto compute = [&](int b) {
        uint32_t ab = sb + b * 10240 + (wm + lrow) * 80 + lk * 2;
        uint32_t bb = sb + 20480 + b * 10240 + (wn + lrow) * 80 + lk * 2;
        #pragma unroll
        for (int ks = 0; ks < 2; ks++) {
            uint32_t koff = ks * 32;  // 16 halves = 32B
            uint32_t bf[2][4];
            #pragma unroll
            for (int p = 0; p < 2; p++)
                LDSM_X4(bf[p], bb + p * (16 * 80) + koff);   // B is [n][k]: non-trans
            #pragma unroll
            for (int mt = 0; mt < 4; mt++) {
                uint32_t af[4];
                LDSM_X4(af, ab + mt * (16 * 80) + koff);
                #pragma unroll
                for (int p = 0; p < 2; p++) {
                    MMA_16816(acc[mt][2 * p],     af, bf[p][0], bf[p][2]);
                    MMA_16816(acc[mt][2 * p + 1], af, bf[p][1], bf[p][3]);
                }
            }
        }
    };

    load_chunk(0);
    CP_COMMIT();
    for (int c = 0; c < nch; c++) {
        if (c + 1 < nch) {
            load_chunk(c + 1);
            CP_COMMIT();
            CP_WAIT1();
        } else {
            CP_WAIT0();
        }
        __syncthreads();
        compute(c & 1);
        __syncthreads();
    }

    // ---- epilogue: store C + fused attention partial dots ----
    const int g = lane >> 2, iq = lane & 3;
    float asv[8], adv[8];
    #pragma unroll
    for (int nt = 0; nt < 4; nt++) {
        int cidx = col0 + wn + nt * 8 + iq * 2;
        asv[2 * nt]     = __ldg(asrc + cidx);
        asv[2 * nt + 1] = __ldg(asrc + cidx + 1);
        adv[2 * nt]     = __ldg(adst + cidx);
        adv[2 * nt + 1] = __ldg(adst + cidx + 1);
    }
    const int head = col0 >> cshift;   // tile never crosses a head boundary
    #pragma unroll
    for (int mt = 0; mt < 4; mt++) {
        int r1 = row0 + wm + mt * 16 + g;
        int r2 = r1 + 8;
        float s1a = 0.f, s2a = 0.f, s1b = 0.f, s2b = 0.f;
        #pragma unroll
        for (int nt = 0; nt < 4; nt++) {
            float v0 = acc[mt][nt][0], v1 = acc[mt][nt][1];
            float w0 = acc[mt][nt][2], w1 = acc[mt][nt][3];
            s1a += v0 * asv[2 * nt] + v1 * asv[2 * nt + 1];
            s2a += v0 * adv[2 * nt] + v1 * adv[2 * nt + 1];
            s1b += w0 * asv[2 * nt] + w1 * asv[2 * nt + 1];
            s2b += w0 * adv[2 * nt] + w1 * adv[2 * nt + 1];
            int cc = col0 + wn + nt * 8 + iq * 2;
            if (r1 < NNODES) *(float2*)(C + (size_t)r1 * Nc + cc) = make_float2(v0, v1);
            if (r2 < NNODES) *(float2*)(C + (size_t)r2 * Nc + cc) = make_float2(w0, w1);
        }
        #pragma unroll
        for (int o = 1; o <= 2; o <<= 1) {
            s1a += __shfl_xor_sync(0xffffffffu, s1a, o);
            s2a += __shfl_xor_sync(0xffffffffu, s2a, o);
            s1b += __shfl_xor_sync(0xffffffffu, s1b, o);
            s2b += __shfl_xor_sync(0xffffffffu, s2b, o);
        }
        if (iq == 0) {
            if (r1 < NNODES) {
                atomicAdd(&d_AS[r1 * 4 + head], s1a);
                atomicAdd(&d_AD[r1 * 4 + head], s2a);
            }
            if (r2 < NNODES) {
                atomicAdd(&d_AS[r2 * 4 + head], s1b);
                atomicAdd(&d_AD[r2 * 4 + head], s2b);
            }
        }
    }
}

// ---------------- fused softmax + gather-aggregate (one block per dst node) ----------------
__global__ __launch_bounds__(256) void k_agg(const float* __restrict__ bg,
                                             int hc, int cshift, int coff) {
    int n = blockIdx.x;
    int tid = threadIdx.x;
    int lane = tid & 31, wid = tid >> 5;
    int rs = d_rowptr[n];
    int deg = d_rowptr[n + 1] - rs;
    int tot = deg + 1;

    __shared__ float s_m[4], s_dinv[4];
    __shared__ float s_red[8];
    __shared__ int   s_src[128];
    __shared__ float s_al[128 * 4];

    float ad[4];
    #pragma unroll
    for (int h = 0; h < 4; h++) ad[h] = d_AD[n * 4 + h];

    float lm[4] = {-1e30f, -1e30f, -1e30f, -1e30f};
    for (int i = tid; i < tot; i += 256) {
        int s = (i < deg) ? d_csr[rs + i] : n;
        #pragma unroll
        for (int h = 0; h < 4; h++) {
            float e = lrelu(d_AS[s * 4 + h] + ad[h]);
            lm[h] = fmaxf(lm[h], e);
        }
    }
    #pragma unroll
    for (int h = 0; h < 4; h++) {
        float v = warpMax(lm[h]);
        if (lane == 0) s_red[wid] = v;
        __syncthreads();
        if (tid == 0) {
            float m = s_red[0];
            #pragma unroll
            for (int w2 = 1; w2 < 8; w2++) m = fmaxf(m, s_red[w2]);
            s_m[h] = m;
        }
        __syncthreads();
    }

    float ls[4] = {0.f, 0.f, 0.f, 0.f};
    for (int i = tid; i < tot; i += 256) {
        int s = (i < deg) ? d_csr[rs + i] : n;
        #pragma unroll
        for (int h = 0; h < 4; h++) {
            float e = lrelu(d_AS[s * 4 + h] + ad[h]);
            ls[h] += __expf(e - s_m[h]);
        }
    }
    #pragma unroll
    for (int h = 0; h < 4; h++) {
        float v = warpSum(ls[h]);
        if (lane == 0) s_red[wid] = v;
        __syncthreads();
        if (tid == 0) {
            float t = 0.f;
            #pragma unroll
            for (int w2 = 0; w2 < 8; w2++) t += s_red[w2];
            s_dinv[h] = 1.f / (t + 1e-16f);
        }
        __syncthreads();
    }

    float acc[4] = {0.f, 0.f, 0.f, 0.f};
    int kmax = hc >> 8;
    for (int base = 0; base < tot; base += 128) {
        int cnt = min(128, tot - base);
        if (tid < cnt) {
            int i = base + tid;
            int s = (i < deg) ? d_csr[rs + i] : n;
            s_src[tid] = s;
            #pragma unroll
            for (int h = 0; h < 4; h++) {
                float e = lrelu(d_AS[s * 4 + h] + ad[h]);
                s_al[tid * 4 + h] = __expf(e - s_m[h]) * s_dinv[h];
            }
        }
        __syncthreads();
        for (int j = 0; j < cnt; j++) {
            int s = s_src[j];
            const float* hp = d_H + (size_t)s * hc;
            #pragma unroll
            for (int k = 0; k < 4; k++) {
                if (k < kmax) {
                    int c = tid + (k << 8);
                    acc[k] = fmaf(s_al[j * 4 + (c >> cshift)], hp[c], acc[k]);
                }
            }
        }
        __syncthreads();
    }
    float* outp = d_F + (size_t)n * DOUT + coff;
    #pragma unroll
    for (int k = 0; k < 4; k++) {
        if (k < kmax) {
            int c = tid + (k << 8);
            outp[c] = acc[k] + bg[c];
        }
    }
}

// ---------------- pooling ----------------
__global__ void k_pool() {
    int g = blockIdx.x;
    for (int c = threadIdx.x; c < DOUT; c += 256) {
        const float* p = d_F + (size_t)g * NPG * DOUT + c;
        float s = 0.f;
        for (int r = 0; r < NPG; r++) {
            float v = p[(size_t)r * DOUT];
            s += v > 0.f ? v : 0.f;
        }
        d_pooled[g * DOUT + c] = s * (1.f / (float)NPG);
    }
}

// ---------------- dense head ----------------
__global__ void k_hbias(const float* __restrict__ bd1) {
    int i = blockIdx.x * 256 + threadIdx.x;
    if (i < NGRAPH * HID) d_h1[i] = bd1[i % HID];
}

__global__ __launch_bounds__(128) void k_dense1(const float* __restrict__ Wd1) {
    __shared__ float sW[64][128];
    __shared__ float sp[64];
    int j0 = blockIdx.x * 128, k0 = blockIdx.y * 64;
    int j = threadIdx.x;
    for (int i = 0; i < 64; i++)
        sW[i][j] = Wd1[(size_t)(k0 + i) * HID + j0 + j];
    __syncthreads();
    for (int g = 0; g < NGRAPH; g++) {
        if (j < 64) sp[j] = d_pooled[g * DOUT + k0 + j];
        __syncthreads();
        float a = 0.f;
        #pragma unroll
        for (int k = 0; k < 64; k++) a = fmaf(sp[k], sW[k][j], a);
        atomicAdd(&d_h1[g * HID + j0 + j], a);
        __syncthreads();
    }
}

// ---------------- relu + layernorm + final linear ----------------
__global__ void k_final(const float* __restrict__ gln, const float* __restrict__ bln,
                        const float* __restrict__ Wd2, const float* __restrict__ bd2,
                        float* __restrict__ out) {
    int g = blockIdx.x;
    int tid = threadIdx.x, lane = tid & 31, wid = tid >> 5;
    __shared__ float sred[8];
    __shared__ float s_mu, s_rstd;
    const float* h = d_h1 + g * HID;

    float s = 0.f;
    for (int j = tid; j < HID; j += 256) s += fmaxf(h[j], 0.f);
    s = warpSum(s);
    if (lane == 0) sred[wid] = s;
    __syncthreads();
    if (tid == 0) {
        float t = 0.f;
        #pragma unroll
        for (int w = 0; w < 8; w++) t += sred[w];
        s_mu = t / (float)HID;
    }
    __syncthreads();
    float mu = s_mu;

    float v = 0.f;
    for (int j = tid; j < HID; j += 256) {
        float d = fmaxf(h[j], 0.f) - mu;
        v = fmaf(d, d, v);
    }
    v = warpSum(v);
    if (lane == 0) sred[wid] = v;
    __syncthreads();
    if (tid == 0) {
        float t = 0.f;
        #pragma unroll
        for (int w = 0; w < 8; w++) t += sred[w];
        s_rstd = rsqrtf(t / (float)HID + 1e-5f);
    }
    __syncthreads();
    float rstd = s_rstd;

    float dot = 0.f;
    for (int j = tid; j < HID; j += 256) {
        float xn = (fmaxf(h[j], 0.f) - mu) * rstd * gln[j] + bln[j];
        dot = fmaf(xn, Wd2[j], dot);
    }
    dot = warpSum(dot);
    if (lane == 0) sred[wid] = dot;
    __syncthreads();
    if (tid == 0) {
        float t = 0.f;
        #pragma unroll
        for (int w = 0; w < 8; w++) t += sred[w];
        out[g] = t + bd2[0] + 0.5f;
    }
}

// ---------------- launch ----------------
extern "C" void kernel_launch(void* const* d_in, const int* in_sizes, int n_in,
                              void* d_out, int out_size) {
    const float* x   = (const float*)d_in[0];
    const int*   ei  = (const int*)d_in[1];
    const float* Wg[4]  = {(const float*)d_in[3],  (const float*)d_in[7],
                           (const float*)d_in[11], (const float*)d_in[15]};
    const float* as[4]  = {(const float*)d_in[4],  (const float*)d_in[8],
                           (const float*)d_in[12], (const float*)d_in[16]};
    const float* adp[4] = {(const float*)d_in[5],  (const float*)d_in[9],
                           (const float*)d_in[13], (const float*)d_in[17]};
    const float* bgp[4] = {(const float*)d_in[6],  (const float*)d_in[10],
                           (const float*)d_in[14], (const float*)d_in[18]};
    const float* Wd1 = (const float*)d_in[19];
    const float* bd1 = (const float*)d_in[20];
    const float* gln = (const float*)d_in[21];
    const float* bln = (const float*)d_in[22];
    const float* Wd2 = (const float*)d_in[23];
    const float* bd2 = (const float*)d_in[24];

    float* dF; float* dH; __nv_bfloat16* dA2; __nv_bfloat16* dW2;
    cudaGetSymbolAddress((void**)&dF, d_F);
    cudaGetSymbolAddress((void**)&dH, d_H);
    cudaGetSymbolAddress((void**)&dA2, d_A2);
    cudaGetSymbolAddress((void**)&dW2, d_W2);

    // CSR build (dst-grouped)
    k_zero<<<(NNODES + 255) / 256, 256>>>();
    k_count<<<(NEDGES + 255) / 256, 256>>>(ei);
    k_scan<<<1, 1024>>>();
    k_fill<<<(NEDGES + 255) / 256, 256>>>(ei);

    // layer configs
    const int Kl[4]   = {768, 512, 512, 1024};
    const int Ncl[4]  = {512, 512, 1024, 1024};
    const int woff[4] = {0, 786432, 1310720, 2359296};
    const int coff[4] = {0, 512, 1024, 2048};
    const int csh[4]  = {7, 7, 8, 8};

    // W prep (hi/lo split + transpose), once per launch
    for (int l = 0; l < 4; l++) {
        dim3 g(Ncl[l] / 32, Kl[l] / 32);
        k_prepw<<<g, 256>>>(Wg[l], dW2 + woff[l], Kl[l], Ncl[l]);
    }

    for (int l = 0; l < 4; l++) {
        int K = Kl[l], Nc = Ncl[l];
        const float* Ain = (l == 0) ? x : (dF + coff[l - 1]);
        int lda = (l == 0) ? 768 : DOUT;
        k_zatt<<<(NNODES * 4 + 255) / 256, 256>>>();
        k_cvt<<<dim3(K / 256, NNODES), 256>>>(Ain, lda, K);
        dim3 gg(Nc / 128, MPAD / 128);
        k_gemm_mma<<<gg, 256>>>(dA2, dW2 + woff[l], dH, K, Nc,
                                as[l], adp[l], csh[l]);
        k_agg<<<NNODES, 256>>>(bgp[l], Nc, csh[l], coff[l]);
    }

    // head
    k_pool<<<NGRAPH, 256>>>();
    k_hbias<<<(NGRAPH * HID + 255) / 256, 256>>>(bd1);
    k_dense1<<<dim3(HID / 128, DOUT / 64), 128>>>(Wd1);
    k_final<<<NGRAPH, 256>>>(gln, bln, Wd2, bd2, (float*)d_out);
}

// round 5
// speedup vs baseline: 2.1055x; 1.2875x over previous
#include <cuda_runtime.h>
#include <cuda_bf16.h>
#include <math.h>
#include <stdint.h>

#define NNODES 40000
#define MPAD   40064
#define NEDGES 480000
#define NGRAPH 160
#define NPG    250
#define DOUT   3072
#define HID    1536

// ---------------- scratch (device globals) ----------------
__device__ float d_F[(size_t)NNODES * DOUT];     // concat buffer: c1|c2|c3|c4
__device__ float d_H[(size_t)NNODES * 1024];     // per-layer GEMM output h = x@W
__device__ __nv_bfloat16 d_A2[(size_t)MPAD * 2048];  // A split [M, 2K]: [hi | lo]
__device__ __nv_bfloat16 d_W2[4456448];          // per-layer W^T split [N, 2K]
__device__ float d_AS[NNODES * 4];
__device__ float d_AD[NNODES * 4];
__device__ float d_alpha[(size_t)NEDGES * 4];    // per-edge attention (CSR order)
__device__ float d_aself[NNODES * 4];            // self-loop attention
__device__ int   d_rowptr[NNODES + 1];
__device__ int   d_deg[NNODES];
__device__ int   d_cur[NNODES];
__device__ int   d_csr[NEDGES];
__device__ float d_pooled[NGRAPH * DOUT];
__device__ float d_h1[NGRAPH * HID];

// ---------------- ptx helpers (baseline ISA only: sm_80-era) ----------------
__device__ __forceinline__ uint32_t smem_u32(const void* p) {
    uint32_t a;
    asm("{ .reg .u64 t; cvta.to.shared.u64 t, %1; cvt.u32.u64 %0, t; }" : "=r"(a) : "l"(p));
    return a;
}

#define CP_ASYNC16(dst, src) \
    asm volatile("cp.async.cg.shared.global [%0], [%1], 16;" :: "r"(dst), "l"(src))
#define CP_ASYNC16_Z(dst, src, szp) \
    asm volatile("cp.async.cg.shared.global [%0], [%1], 16, %2;" :: "r"(dst), "l"(src), "r"(szp))
#define CP_COMMIT() asm volatile("cp.async.commit_group;" ::: "memory")
#define CP_WAIT1()  asm volatile("cp.async.wait_group 1;" ::: "memory")
#define CP_WAIT0()  asm volatile("cp.async.wait_group 0;" ::: "memory")

#define LDSM_X4(r, addr) \
    asm volatile("ldmatrix.sync.aligned.m8n8.x4.shared.b16 {%0,%1,%2,%3}, [%4];" \
        : "=r"((r)[0]), "=r"((r)[1]), "=r"((r)[2]), "=r"((r)[3]) : "r"(addr))

#define MMA_16816(d, a, b0, b1) \
    asm volatile("mma.sync.aligned.m16n8k16.row.col.f32.bf16.bf16.f32 " \
        "{%0,%1,%2,%3}, {%4,%5,%6,%7}, {%8,%9}, {%0,%1,%2,%3};" \
        : "+f"((d)[0]), "+f"((d)[1]), "+f"((d)[2]), "+f"((d)[3]) \
        : "r"((a)[0]), "r"((a)[1]), "r"((a)[2]), "r"((a)[3]), "r"(b0), "r"(b1))

// ---------------- small helpers ----------------
__device__ __forceinline__ float warpSum(float v) {
    #pragma unroll
    for (int o = 16; o; o >>= 1) v += __shfl_xor_sync(0xffffffffu, v, o);
    return v;
}
__device__ __forceinline__ float warpMax(float v) {
    #pragma unroll
    for (int o = 16; o; o >>= 1) v = fmaxf(v, __shfl_xor_sync(0xffffffffu, v, o));
    return v;
}
__device__ __forceinline__ float lrelu(float x) { return x > 0.f ? x : 0.2f * x; }

// ---------------- CSR build ----------------
__global__ void k_zero() {
    int i = blockIdx.x * blockDim.x + threadIdx.x;
    if (i < NNODES) { d_deg[i] = 0; d_cur[i] = 0; }
}
__global__ void k_count(const int* __restrict__ ei) {
    int e = blockIdx.x * blockDim.x + threadIdx.x;
    if (e < NEDGES) atomicAdd(&d_deg[ei[NEDGES + e]], 1);
}
__global__ void k_scan() {
    __shared__ int s[1024];
    __shared__ int s_carry;
    int tid = threadIdx.x;
    if (tid == 0) s_carry = 0;
    __syncthreads();
    for (int base = 0; base < NNODES; base += 1024) {
        int v = (base + tid < NNODES) ? d_deg[base + tid] : 0;
        s[tid] = v;
        __syncthreads();
        for (int off = 1; off < 1024; off <<= 1) {
            int t = (tid >= off) ? s[tid - off] : 0;
            __syncthreads();
            s[tid] += t;
            __syncthreads();
        }
        if (base + tid < NNODES) d_rowptr[base + tid] = s_carry + s[tid] - v;
        __syncthreads();
        if (tid == 0) s_carry += s[1023];
        __syncthreads();
    }
    if (tid == 0) d_rowptr[NNODES] = s_carry;
}
__global__ void k_fill(const int* __restrict__ ei) {
    int e = blockIdx.x * blockDim.x + threadIdx.x;
    if (e < NEDGES) {
        int sn = ei[e];
        int dn = ei[NEDGES + e];
        int p = d_rowptr[dn] + atomicAdd(&d_cur[dn], 1);
        d_csr[p] = sn;
    }
}

// ---------------- W prep: W[K,Nc] fp32 -> Wt2 [Nc, 2K] bf16 (hi|lo) ----------------
__global__ void k_prepw(const float* __restrict__ W, __nv_bfloat16* __restrict__ out,
                        int K, int Nc) {
    __shared__ float s[32][33];
    int k0 = blockIdx.y * 32, n0 = blockIdx.x * 32;
    int tx = threadIdx.x & 31, ty = threadIdx.x >> 5;   // 256 threads
    #pragma unroll
    for (int i = 0; i < 32; i += 8)
        s[ty + i][tx] = W[(size_t)(k0 + ty + i) * Nc + n0 + tx];
    __syncthreads();
    #pragma unroll
    for (int i = 0; i < 32; i += 8) {
        float v = s[tx][ty + i];
        __nv_bfloat16 hi = __float2bfloat16(v);
        __nv_bfloat16 lo = __float2bfloat16(v - __bfloat162float(hi));
        size_t n = (size_t)(n0 + ty + i);
        out[n * (2 * K) + k0 + tx]     = hi;
        out[n * (2 * K) + K + k0 + tx] = lo;
    }
}

// ---------------- A prep (layer 1 only): x[M,768] fp32 -> d_A2 [M, 1536] ----------------
__global__ void k_cvt(const float* __restrict__ A, int lda, int K) {
    int m = blockIdx.y;
    int k = blockIdx.x * 256 + threadIdx.x;
    float v = A[(size_t)m * lda + k];
    __nv_bfloat16 hi = __float2bfloat16(v);
    __nv_bfloat16 lo = __float2bfloat16(v - __bfloat162float(hi));
    d_A2[(size_t)m * (2 * K) + k]     = hi;
    d_A2[(size_t)m * (2 * K) + K + k] = lo;
}

__global__ void k_zatt() {
    int i = blockIdx.x * 256 + threadIdx.x;
    if (i < NNODES * 4) { d_AS[i] = 0.f; d_AD[i] = 0.f; }
}

// ---------------- HMMA GEMM: C[M,Nc] = A'[M,3K] @ B'[Nc,3K]^T ----------------
__global__ __launch_bounds__(256, 2) void k_gemm_mma(
    const __nv_bfloat16* __restrict__ A2, const __nv_bfloat16* __restrict__ B2,
    float* __restrict__ C, int K, int Nc,
    const float* __restrict__ asrc, const float* __restrict__ adst, int cshift)
{
    __shared__ __align__(16) unsigned char smem[40960];  // A:2x10240, B:2x10240 (80B rows)
    uint32_t sb = smem_u32(smem);
    const int tid = threadIdx.x, wid = tid >> 5, lane = tid & 31;
    const int row0 = blockIdx.y * 128, col0 = blockIdx.x * 128;
    const int lda = 2 * K;
    const int kc = K >> 5;
    const int nch = 3 * kc;      // 3 terms: AhBh + AlBh + AhBl
    const int wm = (wid & 1) * 64;
    const int wn = (wid >> 1) * 32;

    float acc[4][4][4];
    #pragma unroll
    for (int a = 0; a < 4; a++)
        #pragma unroll
        for (int b = 0; b < 4; b++)
            #pragma unroll
            for (int q = 0; q < 4; q++) acc[a][b][q] = 0.f;

    auto load_chunk = [&](int c) {
        int seg = c / kc, kk = c - seg * kc;
        int ak = ((seg == 1) ? K : 0) + kk * 32;
        int bk = ((seg == 2) ? K : 0) + kk * 32;
        int b = c & 1;
        uint32_t ab = sb + b * 10240;
        uint32_t bb = sb + 20480 + b * 10240;
        #pragma unroll
        for (int j = 0; j < 2; j++) {
            int q = j * 256 + tid;
            int r = q >> 2, c16 = q & 3;
            int sz = (row0 + r < NNODES) ? 16 : 0;   // zero-fill M pad rows
            CP_ASYNC16_Z(ab + r * 80 + c16 * 16,
                         A2 + (size_t)(row0 + r) * lda + ak + c16 * 8, sz);
            CP_ASYNC16(bb + r * 80 + c16 * 16,
                       B2 + (size_t)(col0 + r) * lda + bk + c16 * 8);
        }
    };

    const int lrow = lane & 15, lk = (lane >> 4) << 3;

    auto compute = [&](int b) {
        uint32_t ab = sb + b * 10240 + (wm + lrow) * 80 + lk * 2;
        uint32_t bb = sb + 20480 + b * 10240 + (wn + lrow) * 80 + lk * 2;
        #pragma unroll
        for (int ks = 0; ks < 2; ks++) {
            uint32_t koff = ks * 32;
            uint32_t bf[2][4];
            #pragma unroll
            for (int p = 0; p < 2; p++)
                LDSM_X4(bf[p], bb + p * (16 * 80) + koff);   // B is [n][k]: non-trans
            #pragma unroll
            for (int mt = 0; mt < 4; mt++) {
                uint32_t af[4];
                LDSM_X4(af, ab + mt * (16 * 80) + koff);
                #pragma unroll
                for (int p = 0; p < 2; p++) {
                    MMA_16816(acc[mt][2 * p],     af, bf[p][0], bf[p][2]);
                    MMA_16816(acc[mt][2 * p + 1], af, bf[p][1], bf[p][3]);
                }
            }
        }
    };

    load_chunk(0);
    CP_COMMIT();
    for (int c = 0; c < nch; c++) {
        if (c + 1 < nch) {
            load_chunk(c + 1);
            CP_COMMIT();
            CP_WAIT1();
        } else {
            CP_WAIT0();
        }
        __syncthreads();
        compute(c & 1);
        __syncthreads();
    }

    // ---- epilogue: store C + fused attention partial dots ----
    const int g = lane >> 2, iq = lane & 3;
    float asv[8], adv[8];
    #pragma unroll
    for (int nt = 0; nt < 4; nt++) {
        int cidx = col0 + wn + nt * 8 + iq * 2;
        asv[2 * nt]     = __ldg(asrc + cidx);
        asv[2 * nt + 1] = __ldg(asrc + cidx + 1);
        adv[2 * nt]     = __ldg(adst + cidx);
        adv[2 * nt + 1] = __ldg(adst + cidx + 1);
    }
    const int head = col0 >> cshift;
    #pragma unroll
    for (int mt = 0; mt < 4; mt++) {
        int r1 = row0 + wm + mt * 16 + g;
        int r2 = r1 + 8;
        float s1a = 0.f, s2a = 0.f, s1b = 0.f, s2b = 0.f;
        #pragma unroll
        for (int nt = 0; nt < 4; nt++) {
            float v0 = acc[mt][nt][0], v1 = acc[mt][nt][1];
            float w0 = acc[mt][nt][2], w1 = acc[mt][nt][3];
            s1a += v0 * asv[2 * nt] + v1 * asv[2 * nt + 1];
            s2a += v0 * adv[2 * nt] + v1 * adv[2 * nt + 1];
            s1b += w0 * asv[2 * nt] + w1 * asv[2 * nt + 1];
            s2b += w0 * adv[2 * nt] + w1 * adv[2 * nt + 1];
            int cc = col0 + wn + nt * 8 + iq * 2;
            if (r1 < NNODES) *(float2*)(C + (size_t)r1 * Nc + cc) = make_float2(v0, v1);
            if (r2 < NNODES) *(float2*)(C + (size_t)r2 * Nc + cc) = make_float2(w0, w1);
        }
        #pragma unroll
        for (int o = 1; o <= 2; o <<= 1) {
            s1a += __shfl_xor_sync(0xffffffffu, s1a, o);
            s2a += __shfl_xor_sync(0xffffffffu, s2a, o);
            s1b += __shfl_xor_sync(0xffffffffu, s1b, o);
            s2b += __shfl_xor_sync(0xffffffffu, s2b, o);
        }
        if (iq == 0) {
            if (r1 < NNODES) {
                atomicAdd(&d_AS[r1 * 4 + head], s1a);
                atomicAdd(&d_AD[r1 * 4 + head], s2a);
            }
            if (r2 < NNODES) {
                atomicAdd(&d_AS[r2 * 4 + head], s1b);
                atomicAdd(&d_AD[r2 * 4 + head], s2b);
            }
        }
    }
}

// ---------------- alpha: softmax weights per edge (warp per node) ----------------
__global__ __launch_bounds__(256) void k_alpha() {
    int n = blockIdx.x * 8 + (threadIdx.x >> 5);
    if (n >= NNODES) return;
    int lane = threadIdx.x & 31;
    int rs = d_rowptr[n];
    int deg = d_rowptr[n + 1] - rs;
    int tot = deg + 1;

    float ad[4];
    #pragma unroll
    for (int h = 0; h < 4; h++) ad[h] = d_AD[n * 4 + h];

    float m[4] = {-1e30f, -1e30f, -1e30f, -1e30f};
    for (int i = lane; i < tot; i += 32) {
        int s = (i < deg) ? d_csr[rs + i] : n;
        #pragma unroll
        for (int h = 0; h < 4; h++)
            m[h] = fmaxf(m[h], lrelu(d_AS[s * 4 + h] + ad[h]));
    }
    #pragma unroll
    for (int h = 0; h < 4; h++) m[h] = warpMax(m[h]);

    float sum[4] = {0.f, 0.f, 0.f, 0.f};
    for (int i = lane; i < tot; i += 32) {
        int s = (i < deg) ? d_csr[rs + i] : n;
        #pragma unroll
        for (int h = 0; h < 4; h++)
            sum[h] += __expf(lrelu(d_AS[s * 4 + h] + ad[h]) - m[h]);
    }
    #pragma unroll
    for (int h = 0; h < 4; h++) sum[h] = warpSum(sum[h]);

    float dinv[4];
    #pragma unroll
    for (int h = 0; h < 4; h++) dinv[h] = 1.f / (sum[h] + 1e-16f);

    for (int i = lane; i < tot; i += 32) {
        int s = (i < deg) ? d_csr[rs + i] : n;
        float al[4];
        #pragma unroll
        for (int h = 0; h < 4; h++)
            al[h] = __expf(lrelu(d_AS[s * 4 + h] + ad[h]) - m[h]) * dinv[h];
        float4 v = make_float4(al[0], al[1], al[2], al[3]);
        if (i < deg) *(float4*)&d_alpha[(size_t)(rs + i) * 4] = v;
        else         *(float4*)&d_aself[n * 4] = v;
    }
}

// ---------------- gather-aggregate over a 512-channel window ----------------
// writes d_F[n, coff+c] and (optionally) the next layer's bf16 hi/lo operand.
__global__ __launch_bounds__(256) void k_gather(const float* __restrict__ bg,
                                                int hc, int cshift, int coff, int c0,
                                                __nv_bfloat16* __restrict__ a2out, int K2) {
    int n = blockIdx.x;
    int tid = threadIdx.x;
    int rs = d_rowptr[n];
    int deg = d_rowptr[n + 1] - rs;
    int tot = deg + 1;

    __shared__ int   s_src[128];
    __shared__ float s_al[4][128];

    const int c_a = c0 + tid;
    const int c_b = c_a + 256;
    const float* pa = s_al[(c_a >> cshift) & 3];
    const float* pb = s_al[(c_b >> cshift) & 3];

    float acc0 = 0.f, acc1 = 0.f;
    for (int base = 0; base < tot; base += 128) {
        int cnt = min(128, tot - base);
        if (base) __syncthreads();
        if (tid < cnt) {
            int i = base + tid;
            float4 v;
            if (i < deg) {
                s_src[tid] = d_csr[rs + i];
                v = *(const float4*)&d_alpha[(size_t)(rs + i) * 4];
            } else {
                s_src[tid] = n;
                v = *(const float4*)&d_aself[n * 4];
            }
            s_al[0][tid] = v.x; s_al[1][tid] = v.y;
            s_al[2][tid] = v.z; s_al[3][tid] = v.w;
        }
        __syncthreads();
        int j = 0;
        for (; j + 2 <= cnt; j += 2) {
            const float* h0 = d_H + (size_t)s_src[j] * hc;
            const float* h1 = d_H + (size_t)s_src[j + 1] * hc;
            float a0a = pa[j], a0b = pb[j], a1a = pa[j + 1], a1b = pb[j + 1];
            float x0 = h0[c_a], y0 = h0[c_b];
            float x1 = h1[c_a], y1 = h1[c_b];
            acc0 = fmaf(a0a, x0, acc0);
            acc1 = fmaf(a0b, y0, acc1);
            acc0 = fmaf(a1a, x1, acc0);
            acc1 = fmaf(a1b, y1, acc1);
        }
        if (j < cnt) {
            const float* h0 = d_H + (size_t)s_src[j] * hc;
            acc0 = fmaf(pa[j], h0[c_a], acc0);
            acc1 = fmaf(pb[j], h0[c_b], acc1);
        }
    }

    float v0 = acc0 + bg[c_a];
    float v1 = acc1 + bg[c_b];
    d_F[(size_t)n * DOUT + coff + c_a] = v0;
    d_F[(size_t)n * DOUT + coff + c_b] = v1;
    if (a2out) {
        __nv_bfloat16 h0 = __float2bfloat16(v0);
        __nv_bfloat16 h1 = __float2bfloat16(v1);
        size_t base2 = (size_t)n * 2 * K2;
        a2out[base2 + c_a]      = h0;
        a2out[base2 + c_b]      = h1;
        a2out[base2 + K2 + c_a] = __float2bfloat16(v0 - __bfloat162float(h0));
        a2out[base2 + K2 + c_b] = __float2bfloat16(v1 - __bfloat162float(h1));
    }
}

// ---------------- pooling: mean over 250 contiguous nodes, fused ReLU ----------------
__global__ void k_pool() {
    int g = blockIdx.x;
    int c = blockIdx.y * 256 + threadIdx.x;
    const float* p = d_F + (size_t)g * NPG * DOUT + c;
    float s = 0.f;
    #pragma unroll 5
    for (int r = 0; r < NPG; r++) {
        float v = p[(size_t)r * DOUT];
        s += v > 0.f ? v : 0.f;
    }
    d_pooled[g * DOUT + c] = s * (1.f / (float)NPG);
}

// ---------------- dense head ----------------
__global__ void k_hbias(const float* __restrict__ bd1) {
    int i = blockIdx.x * 256 + threadIdx.x;
    if (i < NGRAPH * HID) d_h1[i] = bd1[i % HID];
}

__global__ __launch_bounds__(128) void k_dense1(const float* __restrict__ Wd1) {
    __shared__ float sW[64][128];
    __shared__ float sp[64];
    int j0 = blockIdx.x * 128, k0 = blockIdx.y * 64;
    int j = threadIdx.x;
    for (int i = 0; i < 64; i++)
        sW[i][j] = Wd1[(size_t)(k0 + i) * HID + j0 + j];
    __syncthreads();
    for (int g = 0; g < NGRAPH; g++) {
        if (j < 64) sp[j] = d_pooled[g * DOUT + k0 + j];
        __syncthreads();
        float a = 0.f;
        #pragma unroll
        for (int k = 0; k < 64; k++) a = fmaf(sp[k], sW[k][j], a);
        atomicAdd(&d_h1[g * HID + j0 + j], a);
        __syncthreads();
    }
}

// ---------------- relu + layernorm + final linear ----------------
__global__ void k_final(const float* __restrict__ gln, const float* __restrict__ bln,
                        const float* __restrict__ Wd2, const float* __restrict__ bd2,
                        float* __restrict__ out) {
    int g = blockIdx.x;
    int tid = threadIdx.x, lane = tid & 31, wid = tid >> 5;
    __shared__ float sred[8];
    __shared__ float s_mu, s_rstd;
    const float* h = d_h1 + g * HID;

    float s = 0.f;
    for (int j = tid; j < HID; j += 256) s += fmaxf(h[j], 0.f);
    s = warpSum(s);
    if (lane == 0) sred[wid] = s;
    __syncthreads();
    if (tid == 0) {
        float t = 0.f;
        #pragma unroll
        for (int w = 0; w < 8; w++) t += sred[w];
        s_mu = t / (float)HID;
    }
    __syncthreads();
    float mu = s_mu;

    float v = 0.f;
    for (int j = tid; j < HID; j += 256) {
        float d = fmaxf(h[j], 0.f) - mu;
        v = fmaf(d, d, v);
    }
    v = warpSum(v);
    if (lane == 0) sred[wid] = v;
    __syncthreads();
    if (tid == 0) {
        float t = 0.f;
        #pragma unroll
        for (int w = 0; w < 8; w++) t += sred[w];
        s_rstd = rsqrtf(t / (float)HID + 1e-5f);
    }
    __syncthreads();
    float rstd = s_rstd;

    float dot = 0.f;
    for (int j = tid; j < HID; j += 256) {
        float xn = (fmaxf(h[j], 0.f) - mu) * rstd * gln[j] + bln[j];
        dot = fmaf(xn, Wd2[j], dot);
    }
    dot = warpSum(dot);
    if (lane == 0) sred[wid] = dot;
    __syncthreads();
    if (tid == 0) {
        float t = 0.f;
        #pragma unroll
        for (int w = 0; w < 8; w++) t += sred[w];
        out[g] = t + bd2[0] + 0.5f;
    }
}

// ---------------- launch ----------------
extern "C" void kernel_launch(void* const* d_in, const int* in_sizes, int n_in,
                              void* d_out, int out_size) {
    const float* x   = (const float*)d_in[0];
    const int*   ei  = (const int*)d_in[1];
    const float* Wg[4]  = {(const float*)d_in[3],  (const float*)d_in[7],
                           (const float*)d_in[11], (const float*)d_in[15]};
    const float* as[4]  = {(const float*)d_in[4],  (const float*)d_in[8],
                           (const float*)d_in[12], (const float*)d_in[16]};
    const float* adp[4] = {(const float*)d_in[5],  (const float*)d_in[9],
                           (const float*)d_in[13], (const float*)d_in[17]};
    const float* bgp[4] = {(const float*)d_in[6],  (const float*)d_in[10],
                           (const float*)d_in[14], (const float*)d_in[18]};
    const float* Wd1 = (const float*)d_in[19];
    const float* bd1 = (const float*)d_in[20];
    const float* gln = (const float*)d_in[21];
    const float* bln = (const float*)d_in[22];
    const float* Wd2 = (const float*)d_in[23];
    const float* bd2 = (const float*)d_in[24];

    float* dH; __nv_bfloat16* dA2; __nv_bfloat16* dW2;
    cudaGetSymbolAddress((void**)&dH, d_H);
    cudaGetSymbolAddress((void**)&dA2, d_A2);
    cudaGetSymbolAddress((void**)&dW2, d_W2);

    // CSR build (dst-grouped)
    k_zero<<<(NNODES + 255) / 256, 256>>>();
    k_count<<<(NEDGES + 255) / 256, 256>>>(ei);
    k_scan<<<1, 1024>>>();
    k_fill<<<(NEDGES + 255) / 256, 256>>>(ei);

    // layer configs
    const int Kl[4]   = {768, 512, 512, 1024};
    const int Ncl[4]  = {512, 512, 1024, 1024};
    const int woff[4] = {0, 786432, 1310720, 2359296};
    const int coff[4] = {0, 512, 1024, 2048};
    const int csh[4]  = {7, 7, 8, 8};

    // W prep (hi/lo split + transpose), once per launch
    for (int l = 0; l < 4; l++) {
        dim3 g(Ncl[l] / 32, Kl[l] / 32);
        k_prepw<<<g, 256>>>(Wg[l], dW2 + woff[l], Kl[l], Ncl[l]);
    }

    // layer 1 input conversion (x -> hi/lo bf16)
    k_cvt<<<dim3(768 / 256, NNODES), 256>>>(x, 768, 768);

    for (int l = 0; l < 4; l++) {
        int K = Kl[l], Nc = Ncl[l];
        k_zatt<<<(NNODES * 4 + 255) / 256, 256>>>();
        dim3 gg(Nc / 128, MPAD / 128);
        k_gemm_mma<<<gg, 256>>>(dA2, dW2 + woff[l], dH, K, Nc,
                                as[l], adp[l], csh[l]);
        k_alpha<<<(NNODES + 7) / 8, 256>>>();
        // fused aggregation + next-layer operand conversion
        __nv_bfloat16* a2out = (l < 3) ? dA2 : nullptr;
        int K2 = Nc;   // next layer's K == this layer's output width
        for (int c0 = 0; c0 < Nc; c0 += 512)
            k_gather<<<NNODES, 256>>>(bgp[l], Nc, csh[l], coff[l], c0, a2out, K2);
    }

    // head
    k_pool<<<dim3(NGRAPH, DOUT / 256), 256>>>();
    k_hbias<<<(NGRAPH * HID + 255) / 256, 256>>>(bd1);
    k_dense1<<<dim3(HID / 128, DOUT / 64), 128>>>(Wd1);
    k_final<<<NGRAPH, 256>>>(gln, bln, Wd2, bd2, (float*)d_out);
}

// round 6
// speedup vs baseline: 2.2591x; 1.0730x over previous
#include <cuda_runtime.h>
#include <cuda_bf16.h>
#include <math.h>
#include <stdint.h>

#define NNODES 40000
#define MPAD   40064
#define NEDGES 480000
#define NGRAPH 160
#define NPG    250
#define DOUT   3072
#define HID    1536

// ---------------- scratch (device globals) ----------------
__device__ float d_F[(size_t)NNODES * DOUT];     // concat buffer: c1|c2|c3|c4
__device__ float d_H[(size_t)NNODES * 1024];     // per-layer GEMM output h = x@W
__device__ __nv_bfloat16 d_A2[(size_t)MPAD * 2048];  // A split [M, 2K]: [hi | lo]
__device__ __nv_bfloat16 d_W2[4456448];          // per-layer W^T split [N, 2K]
__device__ float d_AS[NNODES * 4];
__device__ float d_AD[NNODES * 4];
__device__ float d_alpha[(size_t)NEDGES * 4];    // per-edge attention (CSR order)
__device__ float d_aself[NNODES * 4];            // self-loop attention
__device__ int   d_rowptr[NNODES + 1];
__device__ int   d_deg[NNODES];
__device__ int   d_cur[NNODES];
__device__ int   d_csr[NEDGES];
__device__ float d_pooled[NGRAPH * DOUT];
__device__ float d_h1[NGRAPH * HID];

// ---------------- ptx helpers (baseline ISA only: sm_80-era) ----------------
__device__ __forceinline__ uint32_t smem_u32(const void* p) {
    uint32_t a;
    asm("{ .reg .u64 t; cvta.to.shared.u64 t, %1; cvt.u32.u64 %0, t; }" : "=r"(a) : "l"(p));
    return a;
}

#define CP_ASYNC16(dst, src) \
    asm volatile("cp.async.cg.shared.global [%0], [%1], 16;" :: "r"(dst), "l"(src))
#define CP_ASYNC16_Z(dst, src, szp) \
    asm volatile("cp.async.cg.shared.global [%0], [%1], 16, %2;" :: "r"(dst), "l"(src), "r"(szp))
#define CP_COMMIT() asm volatile("cp.async.commit_group;" ::: "memory")
#define CP_WAIT1()  asm volatile("cp.async.wait_group 1;" ::: "memory")
#define CP_WAIT0()  asm volatile("cp.async.wait_group 0;" ::: "memory")

#define LDSM_X4(r, addr) \
    asm volatile("ldmatrix.sync.aligned.m8n8.x4.shared.b16 {%0,%1,%2,%3}, [%4];" \
        : "=r"((r)[0]), "=r"((r)[1]), "=r"((r)[2]), "=r"((r)[3]) : "r"(addr))

#define MMA_16816(d, a, b0, b1) \
    asm volatile("mma.sync.aligned.m16n8k16.row.col.f32.bf16.bf16.f32 " \
        "{%0,%1,%2,%3}, {%4,%5,%6,%7}, {%8,%9}, {%0,%1,%2,%3};" \
        : "+f"((d)[0]), "+f"((d)[1]), "+f"((d)[2]), "+f"((d)[3]) \
        : "r"((a)[0]), "r"((a)[1]), "r"((a)[2]), "r"((a)[3]), "r"(b0), "r"(b1))

// ---------------- small helpers ----------------
__device__ __forceinline__ float warpSum(float v) {
    #pragma unroll
    for (int o = 16; o; o >>= 1) v += __shfl_xor_sync(0xffffffffu, v, o);
    return v;
}
__device__ __forceinline__ float warpMax(float v) {
    #pragma unroll
    for (int o = 16; o; o >>= 1) v = fmaxf(v, __shfl_xor_sync(0xffffffffu, v, o));
    return v;
}
__device__ __forceinline__ float lrelu(float x) { return x > 0.f ? x : 0.2f * x; }

// ---------------- CSR build ----------------
__global__ void k_zero() {
    int i = blockIdx.x * blockDim.x + threadIdx.x;
    if (i < NNODES) { d_deg[i] = 0; d_cur[i] = 0; }
}
__global__ void k_count(const int* __restrict__ ei) {
    int e = blockIdx.x * blockDim.x + threadIdx.x;
    if (e < NEDGES) atomicAdd(&d_deg[ei[NEDGES + e]], 1);
}
__global__ void k_scan() {
    __shared__ int s[1024];
    __shared__ int s_carry;
    int tid = threadIdx.x;
    if (tid == 0) s_carry = 0;
    __syncthreads();
    for (int base = 0; base < NNODES; base += 1024) {
        int v = (base + tid < NNODES) ? d_deg[base + tid] : 0;
        s[tid] = v;
        __syncthreads();
        for (int off = 1; off < 1024; off <<= 1) {
            int t = (tid >= off) ? s[tid - off] : 0;
            __syncthreads();
            s[tid] += t;
            __syncthreads();
        }
        if (base + tid < NNODES) d_rowptr[base + tid] = s_carry + s[tid] - v;
        __syncthreads();
        if (tid == 0) s_carry += s[1023];
        __syncthreads();
    }
    if (tid == 0) d_rowptr[NNODES] = s_carry;
}
__global__ void k_fill(const int* __restrict__ ei) {
    int e = blockIdx.x * blockDim.x + threadIdx.x;
    if (e < NEDGES) {
        int sn = ei[e];
        int dn = ei[NEDGES + e];
        int p = d_rowptr[dn] + atomicAdd(&d_cur[dn], 1);
        d_csr[p] = sn;
    }
}

// ---------------- W prep: W[K,Nc] fp32 -> Wt2 [Nc, 2K] bf16 (hi|lo) ----------------
__global__ void k_prepw(const float* __restrict__ W, __nv_bfloat16* __restrict__ out,
                        int K, int Nc) {
    __shared__ float s[32][33];
    int k0 = blockIdx.y * 32, n0 = blockIdx.x * 32;
    int tx = threadIdx.x & 31, ty = threadIdx.x >> 5;   // 256 threads
    #pragma unroll
    for (int i = 0; i < 32; i += 8)
        s[ty + i][tx] = W[(size_t)(k0 + ty + i) * Nc + n0 + tx];
    __syncthreads();
    #pragma unroll
    for (int i = 0; i < 32; i += 8) {
        float v = s[tx][ty + i];
        __nv_bfloat16 hi = __float2bfloat16(v);
        __nv_bfloat16 lo = __float2bfloat16(v - __bfloat162float(hi));
        size_t n = (size_t)(n0 + ty + i);
        out[n * (2 * K) + k0 + tx]     = hi;
        out[n * (2 * K) + K + k0 + tx] = lo;
    }
}

// ---------------- A prep (layer 1 only): x[M,768] fp32 -> d_A2 [M, 1536] ----------------
__global__ void k_cvt(const float* __restrict__ A, int lda, int K) {
    int m = blockIdx.y;
    int k = blockIdx.x * 256 + threadIdx.x;
    float v = A[(size_t)m * lda + k];
    __nv_bfloat16 hi = __float2bfloat16(v);
    __nv_bfloat16 lo = __float2bfloat16(v - __bfloat162float(hi));
    d_A2[(size_t)m * (2 * K) + k]     = hi;
    d_A2[(size_t)m * (2 * K) + K + k] = lo;
}

__global__ void k_zatt() {
    int i = blockIdx.x * 256 + threadIdx.x;
    if (i < NNODES * 4) { d_AS[i] = 0.f; d_AD[i] = 0.f; }
}

// ---------------- HMMA GEMM: C[M,Nc] = A'[M,3K] @ B'[Nc,3K]^T ----------------
// 128x128 tile. Per K32 step: load 4 tiles (Ah,Al,Bh,Bl), run 3 accumulate
// passes (AhBh, AlBh, AhBl). Double-buffered stages of 40KB (dynamic smem).
#define TILE_B   10240           // 128 rows x 80B (64B data + 16B pad)
#define STAGE_B  (4 * TILE_B)    // Ah | Al | Bh | Bl

__global__ __launch_bounds__(256, 2) void k_gemm_mma(
    const __nv_bfloat16* __restrict__ A2, const __nv_bfloat16* __restrict__ B2,
    float* __restrict__ C, int K, int Nc,
    const float* __restrict__ asrc, const float* __restrict__ adst, int cshift)
{
    extern __shared__ __align__(16) unsigned char smem[];
    uint32_t sb = smem_u32(smem);
    const int tid = threadIdx.x, wid = tid >> 5, lane = tid & 31;
    const int row0 = blockIdx.y * 128, col0 = blockIdx.x * 128;
    const int lda = 2 * K;
    const int nkk = K >> 5;      // K32 steps
    const int wm = (wid & 1) * 64;
    const int wn = (wid >> 1) * 32;

    float acc[4][4][4];
    #pragma unroll
    for (int a = 0; a < 4; a++)
        #pragma unroll
        for (int b = 0; b < 4; b++)
            #pragma unroll
            for (int q = 0; q < 4; q++) acc[a][b][q] = 0.f;

    auto load_kk = [&](int kk) {
        int s = kk & 1;
        uint32_t base = sb + s * STAGE_B;
        int k0 = kk * 32;
        #pragma unroll
        for (int j = 0; j < 2; j++) {
            int q = j * 256 + tid;
            int r = q >> 2, c16 = q & 3;
            uint32_t soff = r * 80 + c16 * 16;
            const __nv_bfloat16* arow = A2 + (size_t)(row0 + r) * lda + k0 + c16 * 8;
            const __nv_bfloat16* brow = B2 + (size_t)(col0 + r) * lda + k0 + c16 * 8;
            int sz = (row0 + r < NNODES) ? 16 : 0;   // zero-fill M pad rows
            CP_ASYNC16_Z(base + soff,              arow,     sz);  // Ah
            CP_ASYNC16_Z(base + TILE_B + soff,     arow + K, sz);  // Al
            CP_ASYNC16(base + 2 * TILE_B + soff,   brow);          // Bh
            CP_ASYNC16(base + 3 * TILE_B + soff,   brow + K);      // Bl
        }
    };

    const int lrow = lane & 15, lk = (lane >> 4) << 3;

    auto pass = [&](uint32_t abase, uint32_t bbase) {
        uint32_t ab = abase + (wm + lrow) * 80 + lk * 2;
        uint32_t bb = bbase + (wn + lrow) * 80 + lk * 2;
        #pragma unroll
        for (int ks = 0; ks < 2; ks++) {
            uint32_t koff = ks * 32;
            uint32_t bf[2][4];
            #pragma unroll
            for (int p = 0; p < 2; p++)
                LDSM_X4(bf[p], bb + p * (16 * 80) + koff);   // B is [n][k]: non-trans
            #pragma unroll
            for (int mt = 0; mt < 4; mt++) {
                uint32_t af[4];
                LDSM_X4(af, ab + mt * (16 * 80) + koff);
                #pragma unroll
                for (int p = 0; p < 2; p++) {
                    MMA_16816(acc[mt][2 * p],     af, bf[p][0], bf[p][2]);
                    MMA_16816(acc[mt][2 * p + 1], af, bf[p][1], bf[p][3]);
                }
            }
        }
    };

    load_kk(0);
    CP_COMMIT();
    for (int kk = 0; kk < nkk; kk++) {
        if (kk + 1 < nkk) {
            load_kk(kk + 1);
            CP_COMMIT();
            CP_WAIT1();
        } else {
            CP_WAIT0();
        }
        __syncthreads();
        uint32_t base = sb + (kk & 1) * STAGE_B;
        pass(base,          base + 2 * TILE_B);   // Ah x Bh
        pass(base + TILE_B, base + 2 * TILE_B);   // Al x Bh
        pass(base,          base + 3 * TILE_B);   // Ah x Bl
        __syncthreads();
    }

    // ---- epilogue: store C + fused attention partial dots ----
    const int g = lane >> 2, iq = lane & 3;
    float asv[8], adv[8];
    #pragma unroll
    for (int nt = 0; nt < 4; nt++) {
        int cidx = col0 + wn + nt * 8 + iq * 2;
        asv[2 * nt]     = __ldg(asrc + cidx);
        asv[2 * nt + 1] = __ldg(asrc + cidx + 1);
        adv[2 * nt]     = __ldg(adst + cidx);
        adv[2 * nt + 1] = __ldg(adst + cidx + 1);
    }
    const int head = col0 >> cshift;
    #pragma unroll
    for (int mt = 0; mt < 4; mt++) {
        int r1 = row0 + wm + mt * 16 + g;
        int r2 = r1 + 8;
        float s1a = 0.f, s2a = 0.f, s1b = 0.f, s2b = 0.f;
        #pragma unroll
        for (int nt = 0; nt < 4; nt++) {
            float v0 = acc[mt][nt][0], v1 = acc[mt][nt][1];
            float w0 = acc[mt][nt][2], w1 = acc[mt][nt][3];
            s1a += v0 * asv[2 * nt] + v1 * asv[2 * nt + 1];
            s2a += v0 * adv[2 * nt] + v1 * adv[2 * nt + 1];
            s1b += w0 * asv[2 * nt] + w1 * asv[2 * nt + 1];
            s2b += w0 * adv[2 * nt] + w1 * adv[2 * nt + 1];
            int cc = col0 + wn + nt * 8 + iq * 2;
            if (r1 < NNODES) *(float2*)(C + (size_t)r1 * Nc + cc) = make_float2(v0, v1);
            if (r2 < NNODES) *(float2*)(C + (size_t)r2 * Nc + cc) = make_float2(w0, w1);
        }
        #pragma unroll
        for (int o = 1; o <= 2; o <<= 1) {
            s1a += __shfl_xor_sync(0xffffffffu, s1a, o);
            s2a += __shfl_xor_sync(0xffffffffu, s2a, o);
            s1b += __shfl_xor_sync(0xffffffffu, s1b, o);
            s2b += __shfl_xor_sync(0xffffffffu, s2b, o);
        }
        if (iq == 0) {
            if (r1 < NNODES) {
                atomicAdd(&d_AS[r1 * 4 + head], s1a);
                atomicAdd(&d_AD[r1 * 4 + head], s2a);
            }
            if (r2 < NNODES) {
                atomicAdd(&d_AS[r2 * 4 + head], s1b);
                atomicAdd(&d_AD[r2 * 4 + head], s2b);
            }
        }
    }
}

// ---------------- alpha: softmax weights per edge (warp per node) ----------------
__global__ __launch_bounds__(256) void k_alpha() {
    int n = blockIdx.x * 8 + (threadIdx.x >> 5);
    if (n >= NNODES) return;
    int lane = threadIdx.x & 31;
    int rs = d_rowptr[n];
    int deg = d_rowptr[n + 1] - rs;
    int tot = deg + 1;

    float ad[4];
    #pragma unroll
    for (int h = 0; h < 4; h++) ad[h] = d_AD[n * 4 + h];

    float m[4] = {-1e30f, -1e30f, -1e30f, -1e30f};
    for (int i = lane; i < tot; i += 32) {
        int s = (i < deg) ? d_csr[rs + i] : n;
        #pragma unroll
        for (int h = 0; h < 4; h++)
            m[h] = fmaxf(m[h], lrelu(d_AS[s * 4 + h] + ad[h]));
    }
    #pragma unroll
    for (int h = 0; h < 4; h++) m[h] = warpMax(m[h]);

    float sum[4] = {0.f, 0.f, 0.f, 0.f};
    for (int i = lane; i < tot; i += 32) {
        int s = (i < deg) ? d_csr[rs + i] : n;
        #pragma unroll
        for (int h = 0; h < 4; h++)
            sum[h] += __expf(lrelu(d_AS[s * 4 + h] + ad[h]) - m[h]);
    }
    #pragma unroll
    for (int h = 0; h < 4; h++) sum[h] = warpSum(sum[h]);

    float dinv[4];
    #pragma unroll
    for (int h = 0; h < 4; h++) dinv[h] = 1.f / (sum[h] + 1e-16f);

    for (int i = lane; i < tot; i += 32) {
        int s = (i < deg) ? d_csr[rs + i] : n;
        float al[4];
        #pragma unroll
        for (int h = 0; h < 4; h++)
            al[h] = __expf(lrelu(d_AS[s * 4 + h] + ad[h]) - m[h]) * dinv[h];
        float4 v = make_float4(al[0], al[1], al[2], al[3]);
        if (i < deg) *(float4*)&d_alpha[(size_t)(rs + i) * 4] = v;
        else         *(float4*)&d_aself[n * 4] = v;
    }
}

// ---------------- gather-aggregate over a 512-channel window ----------------
__global__ __launch_bounds__(256) void k_gather(const float* __restrict__ bg,
                                                int hc, int cshift, int coff, int c0,
                                                __nv_bfloat16* __restrict__ a2out, int K2) {
    int n = blockIdx.x;
    int tid = threadIdx.x;
    int rs = d_rowptr[n];
    int deg = d_rowptr[n + 1] - rs;
    int tot = deg + 1;

    __shared__ int   s_src[128];
    __shared__ float s_al[4][128];

    const int c_a = c0 + tid;
    const int c_b = c_a + 256;
    const float* pa = s_al[(c_a >> cshift) & 3];
    const float* pb = s_al[(c_b >> cshift) & 3];

    float acc0 = 0.f, acc1 = 0.f;
    for (int base = 0; base < tot; base += 128) {
        int cnt = min(128, tot - base);
        if (base) __syncthreads();
        if (tid < cnt) {
            int i = base + tid;
            float4 v;
            if (i < deg) {
                s_src[tid] = d_csr[rs + i];
                v = *(const float4*)&d_alpha[(size_t)(rs + i) * 4];
            } else {
                s_src[tid] = n;
                v = *(const float4*)&d_aself[n * 4];
            }
            s_al[0][tid] = v.x; s_al[1][tid] = v.y;
            s_al[2][tid] = v.z; s_al[3][tid] = v.w;
        }
        __syncthreads();
        int j = 0;
        for (; j + 2 <= cnt; j += 2) {
            const float* h0 = d_H + (size_t)s_src[j] * hc;
            const float* h1 = d_H + (size_t)s_src[j + 1] * hc;
            float a0a = pa[j], a0b = pb[j], a1a = pa[j + 1], a1b = pb[j + 1];
            float x0 = h0[c_a], y0 = h0[c_b];
            float x1 = h1[c_a], y1 = h1[c_b];
            acc0 = fmaf(a0a, x0, acc0);
            acc1 = fmaf(a0b, y0, acc1);
            acc0 = fmaf(a1a, x1, acc0);
            acc1 = fmaf(a1b, y1, acc1);
        }
        if (j < cnt) {
            const float* h0 = d_H + (size_t)s_src[j] * hc;
            acc0 = fmaf(pa[j], h0[c_a], acc0);
            acc1 = fmaf(pb[j], h0[c_b], acc1);
        }
    }

    float v0 = acc0 + bg[c_a];
    float v1 = acc1 + bg[c_b];
    d_F[(size_t)n * DOUT + coff + c_a] = v0;
    d_F[(size_t)n * DOUT + coff + c_b] = v1;
    if (a2out) {
        __nv_bfloat16 h0 = __float2bfloat16(v0);
        __nv_bfloat16 h1 = __float2bfloat16(v1);
        size_t base2 = (size_t)n * 2 * K2;
        a2out[base2 + c_a]      = h0;
        a2out[base2 + c_b]      = h1;
        a2out[base2 + K2 + c_a] = __float2bfloat16(v0 - __bfloat162float(h0));
        a2out[base2 + K2 + c_b] = __float2bfloat16(v1 - __bfloat162float(h1));
    }
}

// ---------------- pooling: mean over 250 contiguous nodes, fused ReLU ----------------
__global__ void k_pool() {
    int g = blockIdx.x;
    int c = blockIdx.y * 256 + threadIdx.x;
    const float* p = d_F + (size_t)g * NPG * DOUT + c;
    float s = 0.f;
    #pragma unroll 5
    for (int r = 0; r < NPG; r++) {
        float v = p[(size_t)r * DOUT];
        s += v > 0.f ? v : 0.f;
    }
    d_pooled[g * DOUT + c] = s * (1.f / (float)NPG);
}

// ---------------- dense head ----------------
__global__ void k_hbias(const float* __restrict__ bd1) {
    int i = blockIdx.x * 256 + threadIdx.x;
    if (i < NGRAPH * HID) d_h1[i] = bd1[i % HID];
}

__global__ __launch_bounds__(128) void k_dense1(const float* __restrict__ Wd1) {
    __shared__ float sW[64][128];
    __shared__ float sp[64];
    int j0 = blockIdx.x * 128, k0 = blockIdx.y * 64;
    int j = threadIdx.x;
    for (int i = 0; i < 64; i++)
        sW[i][j] = Wd1[(size_t)(k0 + i) * HID + j0 + j];
    __syncthreads();
    for (int g = 0; g < NGRAPH; g++) {
        if (j < 64) sp[j] = d_pooled[g * DOUT + k0 + j];
        __syncthreads();
        float a = 0.f;
        #pragma unroll
        for (int k = 0; k < 64; k++) a = fmaf(sp[k], sW[k][j], a);
        atomicAdd(&d_h1[g * HID + j0 + j], a);
        __syncthreads();
    }
}

// ---------------- relu + layernorm + final linear ----------------
__global__ void k_final(const float* __restrict__ gln, const float* __restrict__ bln,
                        const float* __restrict__ Wd2, const float* __restrict__ bd2,
                        float* __restrict__ out) {
    int g = blockIdx.x;
    int tid = threadIdx.x, lane = tid & 31, wid = tid >> 5;
    __shared__ float sred[8];
    __shared__ float s_mu, s_rstd;
    const float* h = d_h1 + g * HID;

    float s = 0.f;
    for (int j = tid; j < HID; j += 256) s += fmaxf(h[j], 0.f);
    s = warpSum(s);
    if (lane == 0) sred[wid] = s;
    __syncthreads();
    if (tid == 0) {
        float t = 0.f;
        #pragma unroll
        for (int w = 0; w < 8; w++) t += sred[w];
        s_mu = t / (float)HID;
    }
    __syncthreads();
    float mu = s_mu;

    float v = 0.f;
    for (int j = tid; j < HID; j += 256) {
        float d = fmaxf(h[j], 0.f) - mu;
        v = fmaf(d, d, v);
    }
    v = warpSum(v);
    if (lane == 0) sred[wid] = v;
    __syncthreads();
    if (tid == 0) {
        float t = 0.f;
        #pragma unroll
        for (int w = 0; w < 8; w++) t += sred[w];
        s_rstd = rsqrtf(t / (float)HID + 1e-5f);
    }
    __syncthreads();
    float rstd = s_rstd;

    float dot = 0.f;
    for (int j = tid; j < HID; j += 256) {
        float xn = (fmaxf(h[j], 0.f) - mu) * rstd * gln[j] + bln[j];
        dot = fmaf(xn, Wd2[j], dot);
    }
    dot = warpSum(dot);
    if (lane == 0) sred[wid] = dot;
    __syncthreads();
    if (tid == 0) {
        float t = 0.f;
        #pragma unroll
        for (int w = 0; w < 8; w++) t += sred[w];
        out[g] = t + bd2[0] + 0.5f;
    }
}

// ---------------- launch ----------------
extern "C" void kernel_launch(void* const* d_in, const int* in_sizes, int n_in,
                              void* d_out, int out_size) {
    const float* x   = (const float*)d_in[0];
    const int*   ei  = (const int*)d_in[1];
    const float* Wg[4]  = {(const float*)d_in[3],  (const float*)d_in[7],
                           (const float*)d_in[11], (const float*)d_in[15]};
    const float* as[4]  = {(const float*)d_in[4],  (const float*)d_in[8],
                           (const float*)d_in[12], (const float*)d_in[16]};
    const float* adp[4] = {(const float*)d_in[5],  (const float*)d_in[9],
                           (const float*)d_in[13], (const float*)d_in[17]};
    const float* bgp[4] = {(const float*)d_in[6],  (const float*)d_in[10],
                           (const float*)d_in[14], (const float*)d_in[18]};
    const float* Wd1 = (const float*)d_in[19];
    const float* bd1 = (const float*)d_in[20];
    const float* gln = (const float*)d_in[21];
    const float* bln = (const float*)d_in[22];
    const float* Wd2 = (const float*)d_in[23];
    const float* bd2 = (const float*)d_in[24];

    float* dH; __nv_bfloat16* dA2; __nv_bfloat16* dW2;
    cudaGetSymbolAddress((void**)&dH, d_H);
    cudaGetSymbolAddress((void**)&dA2, d_A2);
    cudaGetSymbolAddress((void**)&dW2, d_W2);

    // opt-in to >48KB dynamic smem (idempotent; not a stream op)
    cudaFuncSetAttribute(k_gemm_mma, cudaFuncAttributeMaxDynamicSharedMemorySize,
                         2 * STAGE_B);

    // CSR build (dst-grouped)
    k_zero<<<(NNODES + 255) / 256, 256>>>();
    k_count<<<(NEDGES + 255) / 256, 256>>>(ei);
    k_scan<<<1, 1024>>>();
    k_fill<<<(NEDGES + 255) / 256, 256>>>(ei);

    // layer configs
    const int Kl[4]   = {768, 512, 512, 1024};
    const int Ncl[4]  = {512, 512, 1024, 1024};
    const int woff[4] = {0, 786432, 1310720, 2359296};
    const int coff[4] = {0, 512, 1024, 2048};
    const int csh[4]  = {7, 7, 8, 8};

    // W prep (hi/lo split + transpose), once per launch
    for (int l = 0; l < 4; l++) {
        dim3 g(Ncl[l] / 32, Kl[l] / 32);
        k_prepw<<<g, 256>>>(Wg[l], dW2 + woff[l], Kl[l], Ncl[l]);
    }

    // layer 1 input conversion (x -> hi/lo bf16)
    k_cvt<<<dim3(768 / 256, NNODES), 256>>>(x, 768, 768);

    for (int l = 0; l < 4; l++) {
        int K = Kl[l], Nc = Ncl[l];
        k_zatt<<<(NNODES * 4 + 255) / 256, 256>>>();
        dim3 gg(Nc / 128, MPAD / 128);
        k_gemm_mma<<<gg, 256, 2 * STAGE_B>>>(dA2, dW2 + woff[l], dH, K, Nc,
                                             as[l], adp[l], csh[l]);
        k_alpha<<<(NNODES + 7) / 8, 256>>>();
        // fused aggregation + next-layer operand conversion
        __nv_bfloat16* a2out = (l < 3) ? dA2 : nullptr;
        int K2 = Nc;   // next layer's K == this layer's output width
        for (int c0 = 0; c0 < Nc; c0 += 512)
            k_gather<<<NNODES, 256>>>(bgp[l], Nc, csh[l], coff[l], c0, a2out, K2);
    }

    // head
    k_pool<<<dim3(NGRAPH, DOUT / 256), 256>>>();
    k_hbias<<<(NGRAPH * HID + 255) / 256, 256>>>(bd1);
    k_dense1<<<dim3(HID / 128, DOUT / 64), 128>>>(Wd1);
    k_final<<<NGRAPH, 256>>>(gln, bln, Wd2, bd2, (float*)d_out);
}